// round 3
// baseline (speedup 1.0000x reference)
#include <cuda_runtime.h>
#include <math.h>

// Problem constants: B=2, S=2048, D=1024, H=16, HD=64
#define BATCH 2
#define SEQ   2048
#define DMODEL 1024
#define NHEAD 16
#define HDIM  64
#define MROWS (BATCH*SEQ)   // 4096

// Scratch (device globals; no allocation allowed)
__device__ float g_q[BATCH*NHEAD*SEQ*HDIM];   // [B,H,S,HD]
__device__ float g_k[BATCH*NHEAD*SEQ*HDIM];
__device__ float g_v[BATCH*NHEAD*SEQ*HDIM];
__device__ float g_ctx[MROWS*DMODEL];         // [B*S, D]

// ---------------------------------------------------------------------------
// GEMM tile config: 128x128 block tile, BK=16, 256 threads, 8x8 per thread.
// Register double-buffered: next tile's LDGs issued before compute, stored to
// the alternate smem buffer after compute; ONE barrier per K-step.
// ---------------------------------------------------------------------------
#define BM 128
#define BN 128
#define BKK 16
#define NSTEP (DMODEL / BKK)   // 64

// QKV projection: X[4096,1024] @ W[1024,1024] + b, scatter-stored to [B,H,S,HD]
__global__ __launch_bounds__(256) void qkv_kernel(
    const float* __restrict__ X,
    const float* __restrict__ Wq, const float* __restrict__ bq,
    const float* __restrict__ Wk, const float* __restrict__ bk,
    const float* __restrict__ Wv, const float* __restrict__ bv)
{
    __shared__ float As[2][BKK][BM];
    __shared__ float Bs[2][BKK][BN];

    const int which = blockIdx.z;
    const float* W    = (which == 0) ? Wq : (which == 1) ? Wk : Wv;
    const float* bias = (which == 0) ? bq : (which == 1) ? bk : bv;
    float* Out        = (which == 0) ? g_q : (which == 1) ? g_k : g_v;

    const int tid = threadIdx.x;
    const int ty = tid >> 4, tx = tid & 15;
    const int rowBase = blockIdx.y * BM;
    const int colBase = blockIdx.x * BN;

    // Per-thread load coordinates (fixed across K-steps)
    const int a_r0 = tid >> 2,          a_c0 = (tid & 3) * 4;        // A: f = tid
    const int a_r1 = (tid + 256) >> 2,  a_c1 = ((tid + 256) & 3) * 4;
    const int b_r0 = tid >> 5,          b_c0 = (tid & 31) * 4;       // B: f = tid
    const int b_r1 = (tid + 256) >> 5,  b_c1 = ((tid + 256) & 31) * 4;

    const float* Arow0 = X + (size_t)(rowBase + a_r0) * DMODEL;
    const float* Arow1 = X + (size_t)(rowBase + a_r1) * DMODEL;

    float acc[8][8];
    #pragma unroll
    for (int i = 0; i < 8; i++)
        #pragma unroll
        for (int j = 0; j < 8; j++) acc[i][j] = 0.f;

    // Prologue: load tile 0 into smem buffer 0
    {
        float4 va0 = *(const float4*)(Arow0 + a_c0);
        float4 va1 = *(const float4*)(Arow1 + a_c1);
        float4 vb0 = *(const float4*)(W + (size_t)b_r0 * DMODEL + colBase + b_c0);
        float4 vb1 = *(const float4*)(W + (size_t)b_r1 * DMODEL + colBase + b_c1);
        As[0][a_c0 + 0][a_r0] = va0.x; As[0][a_c0 + 1][a_r0] = va0.y;
        As[0][a_c0 + 2][a_r0] = va0.z; As[0][a_c0 + 3][a_r0] = va0.w;
        As[0][a_c1 + 0][a_r1] = va1.x; As[0][a_c1 + 1][a_r1] = va1.y;
        As[0][a_c1 + 2][a_r1] = va1.z; As[0][a_c1 + 3][a_r1] = va1.w;
        *(float4*)(&Bs[0][b_r0][b_c0]) = vb0;
        *(float4*)(&Bs[0][b_r1][b_c1]) = vb1;
    }
    __syncthreads();

    int buf = 0;
    for (int t = 0; t < NSTEP; t++) {
        float4 va0, va1, vb0, vb1;
        if (t + 1 < NSTEP) {
            const int k0n = (t + 1) * BKK;
            va0 = *(const float4*)(Arow0 + k0n + a_c0);
            va1 = *(const float4*)(Arow1 + k0n + a_c1);
            vb0 = *(const float4*)(W + (size_t)(k0n + b_r0) * DMODEL + colBase + b_c0);
            vb1 = *(const float4*)(W + (size_t)(k0n + b_r1) * DMODEL + colBase + b_c1);
        }

        const float (*Ab)[BM] = As[buf];
        const float (*Bb)[BN] = Bs[buf];
        #pragma unroll
        for (int k = 0; k < BKK; k++) {
            float a[8], bb[8];
            *(float4*)&a[0]  = *(const float4*)&Ab[k][ty * 4];
            *(float4*)&a[4]  = *(const float4*)&Ab[k][64 + ty * 4];
            *(float4*)&bb[0] = *(const float4*)&Bb[k][tx * 4];
            *(float4*)&bb[4] = *(const float4*)&Bb[k][64 + tx * 4];
            #pragma unroll
            for (int i = 0; i < 8; i++)
                #pragma unroll
                for (int j = 0; j < 8; j++)
                    acc[i][j] = fmaf(a[i], bb[j], acc[i][j]);
        }

        if (t + 1 < NSTEP) {
            const int nb = buf ^ 1;
            As[nb][a_c0 + 0][a_r0] = va0.x; As[nb][a_c0 + 1][a_r0] = va0.y;
            As[nb][a_c0 + 2][a_r0] = va0.z; As[nb][a_c0 + 3][a_r0] = va0.w;
            As[nb][a_c1 + 0][a_r1] = va1.x; As[nb][a_c1 + 1][a_r1] = va1.y;
            As[nb][a_c1 + 2][a_r1] = va1.z; As[nb][a_c1 + 3][a_r1] = va1.w;
            *(float4*)(&Bs[nb][b_r0][b_c0]) = vb0;
            *(float4*)(&Bs[nb][b_r1][b_c1]) = vb1;
            __syncthreads();
            buf = nb;
        }
    }

    // Epilogue: bias + scatter into [B,H,S,HD]
    #pragma unroll
    for (int i = 0; i < 8; i++) {
        int r = rowBase + ((i < 4) ? (ty * 4 + i) : (64 + ty * 4 + (i - 4)));
        int bIdx = r >> 11;       // / 2048
        int s    = r & 2047;
        #pragma unroll
        for (int j = 0; j < 8; j++) {
            int c = colBase + ((j < 4) ? (tx * 4 + j) : (64 + tx * 4 + (j - 4)));
            int h = c >> 6, hd = c & 63;
            Out[(((size_t)(bIdx * NHEAD + h) * SEQ) + s) * HDIM + hd] = acc[i][j] + bias[c];
        }
    }
}

// Output projection: ctx[4096,1024] @ Wo + bo -> out (plain row-major store)
__global__ __launch_bounds__(256) void proj_kernel(
    const float* __restrict__ Wo, const float* __restrict__ bo,
    float* __restrict__ Out)
{
    __shared__ float As[2][BKK][BM];
    __shared__ float Bs[2][BKK][BN];

    const int tid = threadIdx.x;
    const int ty = tid >> 4, tx = tid & 15;
    const int rowBase = blockIdx.y * BM;
    const int colBase = blockIdx.x * BN;

    const int a_r0 = tid >> 2,          a_c0 = (tid & 3) * 4;
    const int a_r1 = (tid + 256) >> 2,  a_c1 = ((tid + 256) & 3) * 4;
    const int b_r0 = tid >> 5,          b_c0 = (tid & 31) * 4;
    const int b_r1 = (tid + 256) >> 5,  b_c1 = ((tid + 256) & 31) * 4;

    const float* Arow0 = g_ctx + (size_t)(rowBase + a_r0) * DMODEL;
    const float* Arow1 = g_ctx + (size_t)(rowBase + a_r1) * DMODEL;

    float acc[8][8];
    #pragma unroll
    for (int i = 0; i < 8; i++)
        #pragma unroll
        for (int j = 0; j < 8; j++) acc[i][j] = 0.f;

    {
        float4 va0 = *(const float4*)(Arow0 + a_c0);
        float4 va1 = *(const float4*)(Arow1 + a_c1);
        float4 vb0 = *(const float4*)(Wo + (size_t)b_r0 * DMODEL + colBase + b_c0);
        float4 vb1 = *(const float4*)(Wo + (size_t)b_r1 * DMODEL + colBase + b_c1);
        As[0][a_c0 + 0][a_r0] = va0.x; As[0][a_c0 + 1][a_r0] = va0.y;
        As[0][a_c0 + 2][a_r0] = va0.z; As[0][a_c0 + 3][a_r0] = va0.w;
        As[0][a_c1 + 0][a_r1] = va1.x; As[0][a_c1 + 1][a_r1] = va1.y;
        As[0][a_c1 + 2][a_r1] = va1.z; As[0][a_c1 + 3][a_r1] = va1.w;
        *(float4*)(&Bs[0][b_r0][b_c0]) = vb0;
        *(float4*)(&Bs[0][b_r1][b_c1]) = vb1;
    }
    __syncthreads();

    int buf = 0;
    for (int t = 0; t < NSTEP; t++) {
        float4 va0, va1, vb0, vb1;
        if (t + 1 < NSTEP) {
            const int k0n = (t + 1) * BKK;
            va0 = *(const float4*)(Arow0 + k0n + a_c0);
            va1 = *(const float4*)(Arow1 + k0n + a_c1);
            vb0 = *(const float4*)(Wo + (size_t)(k0n + b_r0) * DMODEL + colBase + b_c0);
            vb1 = *(const float4*)(Wo + (size_t)(k0n + b_r1) * DMODEL + colBase + b_c1);
        }

        const float (*Ab)[BM] = As[buf];
        const float (*Bb)[BN] = Bs[buf];
        #pragma unroll
        for (int k = 0; k < BKK; k++) {
            float a[8], bb[8];
            *(float4*)&a[0]  = *(const float4*)&Ab[k][ty * 4];
            *(float4*)&a[4]  = *(const float4*)&Ab[k][64 + ty * 4];
            *(float4*)&bb[0] = *(const float4*)&Bb[k][tx * 4];
            *(float4*)&bb[4] = *(const float4*)&Bb[k][64 + tx * 4];
            #pragma unroll
            for (int i = 0; i < 8; i++)
                #pragma unroll
                for (int j = 0; j < 8; j++)
                    acc[i][j] = fmaf(a[i], bb[j], acc[i][j]);
        }

        if (t + 1 < NSTEP) {
            const int nb = buf ^ 1;
            As[nb][a_c0 + 0][a_r0] = va0.x; As[nb][a_c0 + 1][a_r0] = va0.y;
            As[nb][a_c0 + 2][a_r0] = va0.z; As[nb][a_c0 + 3][a_r0] = va0.w;
            As[nb][a_c1 + 0][a_r1] = va1.x; As[nb][a_c1 + 1][a_r1] = va1.y;
            As[nb][a_c1 + 2][a_r1] = va1.z; As[nb][a_c1 + 3][a_r1] = va1.w;
            *(float4*)(&Bs[nb][b_r0][b_c0]) = vb0;
            *(float4*)(&Bs[nb][b_r1][b_c1]) = vb1;
            __syncthreads();
            buf = nb;
        }
    }

    #pragma unroll
    for (int i = 0; i < 8; i++) {
        int r = rowBase + ((i < 4) ? (ty * 4 + i) : (64 + ty * 4 + (i - 4)));
        #pragma unroll
        for (int j = 0; j < 8; j++) {
            int c = colBase + ((j < 4) ? (tx * 4 + j) : (64 + tx * 4 + (j - 4)));
            Out[(size_t)r * DMODEL + c] = acc[i][j] + bo[c];
        }
    }
}

// ---------------------------------------------------------------------------
// Flash attention: per block, one (b, h, 64-row Q tile).
// Online softmax over 32 K/V tiles of 64 rows. All fp32.
// Smem: Qs/Ks/Vs/Ps, each 64 rows x stride 68 floats (69,632 B dynamic).
// ---------------------------------------------------------------------------
#define AST 68                      // smem row stride (floats), 16B-aligned, bank-offset 4
#define ATT_SMEM_FLOATS (4 * 64 * AST)

__global__ __launch_bounds__(256) void attn_kernel(const float* __restrict__ mask)
{
    extern __shared__ float sm[];
    float* Qs = sm;
    float* Ks = sm + 64 * AST;
    float* Vs = sm + 2 * 64 * AST;
    float* Ps = sm + 3 * 64 * AST;

    const int qt = blockIdx.x;     // 0..31
    const int h  = blockIdx.y;     // 0..15
    const int b  = blockIdx.z;     // 0..1
    const int tid = threadIdx.x;
    const int ty = tid >> 4, tx = tid & 15;

    const float* Qg = g_q + ((size_t)(b * NHEAD + h) * SEQ + qt * 64) * HDIM;
    const float* Kg = g_k + (size_t)(b * NHEAD + h) * SEQ * HDIM;
    const float* Vg = g_v + (size_t)(b * NHEAD + h) * SEQ * HDIM;

    // Load Q tile (64 x 64)
    #pragma unroll
    for (int t = 0; t < 4; t++) {
        int f = tid + t * 256;       // 0..1023 float4s
        int r = f >> 4, c4 = f & 15;
        *(float4*)&Qs[r * AST + c4 * 4] = *(const float4*)(Qg + r * HDIM + c4 * 4);
    }

    float m_i[4], l_i[4], o[4][4];
    #pragma unroll
    for (int i = 0; i < 4; i++) {
        m_i[i] = -1e30f; l_i[i] = 0.f;
        #pragma unroll
        for (int j = 0; j < 4; j++) o[i][j] = 0.f;
    }
    __syncthreads();

    for (int kt = 0; kt < SEQ / 64; kt++) {
        // Load K,V tiles
        #pragma unroll
        for (int t = 0; t < 4; t++) {
            int f = tid + t * 256;
            int r = f >> 4, c4 = f & 15;
            *(float4*)&Ks[r * AST + c4 * 4] = *(const float4*)(Kg + (kt * 64 + r) * HDIM + c4 * 4);
            *(float4*)&Vs[r * AST + c4 * 4] = *(const float4*)(Vg + (kt * 64 + r) * HDIM + c4 * 4);
        }
        __syncthreads();

        // S = Q K^T for this thread's 4x4 sub-tile
        float s[4][4];
        #pragma unroll
        for (int i = 0; i < 4; i++)
            #pragma unroll
            for (int j = 0; j < 4; j++) s[i][j] = 0.f;

        #pragma unroll
        for (int d4 = 0; d4 < 16; d4++) {
            float4 qv[4], kv[4];
            #pragma unroll
            for (int i = 0; i < 4; i++) qv[i] = *(float4*)&Qs[(ty * 4 + i) * AST + d4 * 4];
            #pragma unroll
            for (int j = 0; j < 4; j++) kv[j] = *(float4*)&Ks[(tx * 4 + j) * AST + d4 * 4];
            #pragma unroll
            for (int i = 0; i < 4; i++)
                #pragma unroll
                for (int j = 0; j < 4; j++)
                    s[i][j] = fmaf(qv[i].x, kv[j].x,
                              fmaf(qv[i].y, kv[j].y,
                              fmaf(qv[i].z, kv[j].z,
                              fmaf(qv[i].w, kv[j].w, s[i][j]))));
        }

        // scale + additive mask (mask is [B,1,1,S] -> indexed by key position)
        const float* mrow = mask + (size_t)b * SEQ + kt * 64 + tx * 4;
        float mk0 = mrow[0], mk1 = mrow[1], mk2 = mrow[2], mk3 = mrow[3];
        #pragma unroll
        for (int i = 0; i < 4; i++) {
            s[i][0] = s[i][0] * 0.125f + mk0;   // 1/sqrt(64)
            s[i][1] = s[i][1] * 0.125f + mk1;
            s[i][2] = s[i][2] * 0.125f + mk2;
            s[i][3] = s[i][3] * 0.125f + mk3;
        }

        // Online softmax per row (16-lane group within a warp half)
        #pragma unroll
        for (int i = 0; i < 4; i++) {
            float tmax = fmaxf(fmaxf(s[i][0], s[i][1]), fmaxf(s[i][2], s[i][3]));
            #pragma unroll
            for (int mstep = 8; mstep >= 1; mstep >>= 1)
                tmax = fmaxf(tmax, __shfl_xor_sync(0xffffffffu, tmax, mstep));
            float newm = fmaxf(m_i[i], tmax);
            float p0 = __expf(s[i][0] - newm);
            float p1 = __expf(s[i][1] - newm);
            float p2 = __expf(s[i][2] - newm);
            float p3 = __expf(s[i][3] - newm);
            float rsum = p0 + p1 + p2 + p3;
            #pragma unroll
            for (int mstep = 8; mstep >= 1; mstep >>= 1)
                rsum += __shfl_xor_sync(0xffffffffu, rsum, mstep);
            float alpha = __expf(m_i[i] - newm);
            l_i[i] = l_i[i] * alpha + rsum;
            m_i[i] = newm;
            #pragma unroll
            for (int j = 0; j < 4; j++) o[i][j] *= alpha;
            float* prow = &Ps[(ty * 4 + i) * AST + tx * 4];
            prow[0] = p0; prow[1] = p1; prow[2] = p2; prow[3] = p3;
        }
        __syncthreads();

        // O += P * V   (P: 64x64, V: 64x64; this thread: rows ty*4.., cols tx*4..)
        #pragma unroll 4
        for (int kk = 0; kk < 64; kk += 4) {
            float4 pv[4];
            #pragma unroll
            for (int i = 0; i < 4; i++) pv[i] = *(float4*)&Ps[(ty * 4 + i) * AST + kk];
            float4 v0 = *(float4*)&Vs[(kk + 0) * AST + tx * 4];
            float4 v1 = *(float4*)&Vs[(kk + 1) * AST + tx * 4];
            float4 v2 = *(float4*)&Vs[(kk + 2) * AST + tx * 4];
            float4 v3 = *(float4*)&Vs[(kk + 3) * AST + tx * 4];
            #pragma unroll
            for (int i = 0; i < 4; i++) {
                o[i][0] = fmaf(pv[i].x, v0.x, fmaf(pv[i].y, v1.x, fmaf(pv[i].z, v2.x, fmaf(pv[i].w, v3.x, o[i][0]))));
                o[i][1] = fmaf(pv[i].x, v0.y, fmaf(pv[i].y, v1.y, fmaf(pv[i].z, v2.y, fmaf(pv[i].w, v3.y, o[i][1]))));
                o[i][2] = fmaf(pv[i].x, v0.z, fmaf(pv[i].y, v1.z, fmaf(pv[i].z, v2.z, fmaf(pv[i].w, v3.z, o[i][2]))));
                o[i][3] = fmaf(pv[i].x, v0.w, fmaf(pv[i].y, v1.w, fmaf(pv[i].z, v2.w, fmaf(pv[i].w, v3.w, o[i][3]))));
            }
        }
        __syncthreads();   // protect Ks/Vs/Ps before next tile's loads
    }

    // Final normalize and scatter to ctx[B*S, D] with col = h*64+hd
    #pragma unroll
    for (int i = 0; i < 4; i++) {
        int srow = qt * 64 + ty * 4 + i;
        float inv = 1.f / l_i[i];
        #pragma unroll
        for (int j = 0; j < 4; j++) {
            g_ctx[((size_t)b * SEQ + srow) * DMODEL + h * HDIM + tx * 4 + j] = o[i][j] * inv;
        }
    }
}

// ---------------------------------------------------------------------------
extern "C" void kernel_launch(void* const* d_in, const int* in_sizes, int n_in,
                              void* d_out, int out_size)
{
    const float* x    = (const float*)d_in[0];
    const float* mask = (const float*)d_in[1];
    const float* Wq   = (const float*)d_in[2];
    const float* bq   = (const float*)d_in[3];
    const float* Wk   = (const float*)d_in[4];
    const float* bk   = (const float*)d_in[5];
    const float* Wv   = (const float*)d_in[6];
    const float* bv   = (const float*)d_in[7];
    const float* Wo   = (const float*)d_in[8];
    const float* bo   = (const float*)d_in[9];
    float* out = (float*)d_out;

    (void)in_sizes; (void)n_in; (void)out_size;

    // Host-side config (not a stream op; legal under graph capture).
    cudaFuncSetAttribute(attn_kernel, cudaFuncAttributeMaxDynamicSharedMemorySize,
                         ATT_SMEM_FLOATS * (int)sizeof(float));

    // 1) QKV projections (z-dim selects Q/K/V)
    qkv_kernel<<<dim3(DMODEL / BN, MROWS / BM, 3), 256>>>(x, Wq, bq, Wk, bk, Wv, bv);

    // 2) Flash attention
    attn_kernel<<<dim3(SEQ / 64, NHEAD, BATCH), 256,
                  ATT_SMEM_FLOATS * sizeof(float)>>>(mask);

    // 3) Output projection
    proj_kernel<<<dim3(DMODEL / BN, MROWS / BM), 256>>>(Wo, bo, out);
}

// round 7
// speedup vs baseline: 3.5512x; 3.5512x over previous
#include <cuda_runtime.h>
#include <cstdint>
#include <math.h>

// Problem constants: B=2, S=2048, D=1024, H=16, HD=64
#define BATCH 2
#define SEQ   2048
#define DMODEL 1024
#define NHEAD 16
#define HDIM  64
#define MROWS (BATCH*SEQ)   // 4096

// Scratch (device globals; no allocation allowed)
__device__ float g_q[BATCH*NHEAD*SEQ*HDIM];   // [B,H,S,HD]
__device__ float g_k[BATCH*NHEAD*SEQ*HDIM];
__device__ float g_v[BATCH*NHEAD*SEQ*HDIM];
__device__ float g_ctx[MROWS*DMODEL];         // [B*S, D]

// ---------------------------------------------------------------------------
// tf32 round (rna) — applied when staging operands to smem
// ---------------------------------------------------------------------------
__device__ __forceinline__ float tf32r(float x) {
    uint32_t u;
    asm("cvt.rna.tf32.f32 %0, %1;" : "=r"(u) : "f"(x));
    return __uint_as_float(u);
}

// mma.sync m16n8k8 tf32: D(m16n8,f32) += A(m16k8) * B(k8n8)
__device__ __forceinline__ void mma_tf32(float* c,
    uint32_t a0, uint32_t a1, uint32_t a2, uint32_t a3,
    uint32_t b0, uint32_t b1)
{
    asm volatile(
        "mma.sync.aligned.m16n8k8.row.col.f32.tf32.tf32.f32 "
        "{%0,%1,%2,%3}, {%4,%5,%6,%7}, {%8,%9}, {%0,%1,%2,%3};"
        : "+f"(c[0]), "+f"(c[1]), "+f"(c[2]), "+f"(c[3])
        : "r"(a0), "r"(a1), "r"(a2), "r"(a3), "r"(b0), "r"(b1));
}

// ===========================================================================
// Tensor-core GEMM (mma.sync tf32): C[4096,1024] = A @ W (+bias)
// Block tile 128x128, BK=16, 256 threads (8 warps), warp tile 64x32.
// Double-buffered smem, stride 136 floats -> conflict-free fragment LDS.
// MODE 0: A=X, W selected by blockIdx.z, scatter-store to g_q/g_k/g_v
// MODE 1: A=g_ctx, W=Wo, row-major store to OutP
// ===========================================================================
#define BM 128
#define BN 128
#define BKK 16
#define NSTEP (DMODEL / BKK)   // 64
#define ASTRIDE 136

template<int MODE>
__global__ __launch_bounds__(256) void gemm_tc(
    const float* __restrict__ X,
    const float* __restrict__ W0, const float* __restrict__ bias0,
    const float* __restrict__ W1, const float* __restrict__ bias1,
    const float* __restrict__ W2, const float* __restrict__ bias2,
    float* __restrict__ OutP)
{
    __shared__ float As[2][BKK][ASTRIDE];
    __shared__ float Bs[2][BKK][ASTRIDE];

    const int which = (MODE == 0) ? blockIdx.z : 0;
    const float* A    = (MODE == 0) ? X : g_ctx;
    const float* W    = (which == 0) ? W0 : (which == 1) ? W1 : W2;
    const float* bias = (which == 0) ? bias0 : (which == 1) ? bias1 : bias2;

    const int tid = threadIdx.x;
    const int lane = tid & 31;
    const int g   = lane >> 2;          // groupID 0..7
    const int tig = lane & 3;           // thread-in-group 0..3
    const int m0 = ((tid >> 5) & 1) * 64;   // warp row offset (2 x 64)
    const int n0 = ((tid >> 5) >> 1) * 32;  // warp col offset (4 x 32)

    const int rowBase = blockIdx.y * BM;
    const int colBase = blockIdx.x * BN;

    const int a_r0 = tid >> 2,          a_c0 = (tid & 3) * 4;
    const int a_r1 = (tid + 256) >> 2,  a_c1 = ((tid + 256) & 3) * 4;
    const int b_r0 = tid >> 5,          b_c0 = (tid & 31) * 4;
    const int b_r1 = (tid + 256) >> 5,  b_c1 = ((tid + 256) & 31) * 4;

    const float* Arow0 = A + (size_t)(rowBase + a_r0) * DMODEL;
    const float* Arow1 = A + (size_t)(rowBase + a_r1) * DMODEL;

    float acc[4][4][4];
    #pragma unroll
    for (int mf = 0; mf < 4; mf++)
        #pragma unroll
        for (int nf = 0; nf < 4; nf++)
            #pragma unroll
            for (int rgi = 0; rgi < 4; rgi++) acc[mf][nf][rgi] = 0.f;

    // Prologue: tile 0 -> buffer 0 (tf32-rounded)
    {
        float4 va0 = *(const float4*)(Arow0 + a_c0);
        float4 va1 = *(const float4*)(Arow1 + a_c1);
        float4 vb0 = *(const float4*)(W + (size_t)b_r0 * DMODEL + colBase + b_c0);
        float4 vb1 = *(const float4*)(W + (size_t)b_r1 * DMODEL + colBase + b_c1);
        As[0][a_c0 + 0][a_r0] = tf32r(va0.x); As[0][a_c0 + 1][a_r0] = tf32r(va0.y);
        As[0][a_c0 + 2][a_r0] = tf32r(va0.z); As[0][a_c0 + 3][a_r0] = tf32r(va0.w);
        As[0][a_c1 + 0][a_r1] = tf32r(va1.x); As[0][a_c1 + 1][a_r1] = tf32r(va1.y);
        As[0][a_c1 + 2][a_r1] = tf32r(va1.z); As[0][a_c1 + 3][a_r1] = tf32r(va1.w);
        float4 w0; w0.x = tf32r(vb0.x); w0.y = tf32r(vb0.y); w0.z = tf32r(vb0.z); w0.w = tf32r(vb0.w);
        float4 w1; w1.x = tf32r(vb1.x); w1.y = tf32r(vb1.y); w1.z = tf32r(vb1.z); w1.w = tf32r(vb1.w);
        *(float4*)&Bs[0][b_r0][b_c0] = w0;
        *(float4*)&Bs[0][b_r1][b_c1] = w1;
    }
    __syncthreads();

    int buf = 0;
    for (int t = 0; t < NSTEP; t++) {
        float4 va0, va1, vb0, vb1;
        if (t + 1 < NSTEP) {                         // overlap gmem loads with MMA
            const int k0n = (t + 1) * BKK;
            va0 = *(const float4*)(Arow0 + k0n + a_c0);
            va1 = *(const float4*)(Arow1 + k0n + a_c1);
            vb0 = *(const float4*)(W + (size_t)(k0n + b_r0) * DMODEL + colBase + b_c0);
            vb1 = *(const float4*)(W + (size_t)(k0n + b_r1) * DMODEL + colBase + b_c1);
        }

        // Compute: 2 k8 steps x 16 mma
        #pragma unroll
        for (int ks = 0; ks < 2; ks++) {
            const int kb = ks * 8;
            uint32_t af[4][4], bf[4][2];
            #pragma unroll
            for (int mf = 0; mf < 4; mf++) {
                int mm = m0 + mf * 16 + g;
                af[mf][0] = __float_as_uint(As[buf][kb + tig    ][mm]);
                af[mf][1] = __float_as_uint(As[buf][kb + tig    ][mm + 8]);
                af[mf][2] = __float_as_uint(As[buf][kb + tig + 4][mm]);
                af[mf][3] = __float_as_uint(As[buf][kb + tig + 4][mm + 8]);
            }
            #pragma unroll
            for (int nf = 0; nf < 4; nf++) {
                int nn = n0 + nf * 8 + g;
                bf[nf][0] = __float_as_uint(Bs[buf][kb + tig    ][nn]);
                bf[nf][1] = __float_as_uint(Bs[buf][kb + tig + 4][nn]);
            }
            #pragma unroll
            for (int mf = 0; mf < 4; mf++)
                #pragma unroll
                for (int nf = 0; nf < 4; nf++)
                    mma_tf32(acc[mf][nf],
                             af[mf][0], af[mf][1], af[mf][2], af[mf][3],
                             bf[nf][0], bf[nf][1]);
        }

        if (t + 1 < NSTEP) {
            const int nb = buf ^ 1;
            As[nb][a_c0 + 0][a_r0] = tf32r(va0.x); As[nb][a_c0 + 1][a_r0] = tf32r(va0.y);
            As[nb][a_c0 + 2][a_r0] = tf32r(va0.z); As[nb][a_c0 + 3][a_r0] = tf32r(va0.w);
            As[nb][a_c1 + 0][a_r1] = tf32r(va1.x); As[nb][a_c1 + 1][a_r1] = tf32r(va1.y);
            As[nb][a_c1 + 2][a_r1] = tf32r(va1.z); As[nb][a_c1 + 3][a_r1] = tf32r(va1.w);
            float4 w0; w0.x = tf32r(vb0.x); w0.y = tf32r(vb0.y); w0.z = tf32r(vb0.z); w0.w = tf32r(vb0.w);
            float4 w1; w1.x = tf32r(vb1.x); w1.y = tf32r(vb1.y); w1.z = tf32r(vb1.z); w1.w = tf32r(vb1.w);
            *(float4*)&Bs[nb][b_r0][b_c0] = w0;
            *(float4*)&Bs[nb][b_r1][b_c1] = w1;
            __syncthreads();
            buf = nb;
        }
    }

    // Epilogue. C frag: c0=(g,2tig) c1=(g,2tig+1) c2=(g+8,2tig) c3=(g+8,2tig+1)
    #pragma unroll
    for (int mf = 0; mf < 4; mf++) {
        const int rg = rowBase + m0 + mf * 16 + g;
        #pragma unroll
        for (int nf = 0; nf < 4; nf++) {
            const int c = colBase + n0 + nf * 8 + 2 * tig;
            const float* ap = acc[mf][nf];
            #pragma unroll
            for (int rr = 0; rr < 2; rr++) {
                const int r = rg + rr * 8;
                float2 v;
                v.x = ap[rr * 2 + 0] + bias[c];
                v.y = ap[rr * 2 + 1] + bias[c + 1];
                if (MODE == 0) {
                    float* Out = (which == 0) ? g_q : (which == 1) ? g_k : g_v;
                    int bi = r >> 11, s = r & 2047;
                    int h = c >> 6, hd = c & 63;
                    *(float2*)&Out[(((size_t)(bi * NHEAD + h)) * SEQ + s) * HDIM + hd] = v;
                } else {
                    *(float2*)&OutP[(size_t)r * DMODEL + c] = v;
                }
            }
        }
    }
}

// ===========================================================================
// Flash attention on tensor cores (mma.sync tf32).
// 128 threads (4 warps); block = one (b, h, 64-row Q tile); warp = 16 rows.
// K-tile = 64 keys, 32 tiles, online softmax in mma C-fragment layout.
// Smem: Ks[64][68], Vs[64][68], Ps[64][68] (P per-warp-private; doubles as
// Q staging). 52224 B dynamic.
// ===========================================================================
#define BSTR 68
#define ATT_SMEM_BYTES (3 * 64 * BSTR * 4)

__global__ __launch_bounds__(128) void attn_mma(const float* __restrict__ mask)
{
    extern __shared__ float sm[];
    float* Ks = sm;                    // [64][BSTR]
    float* Vs = sm + 64 * BSTR;
    float* Ps = sm + 2 * 64 * BSTR;    // Q staging, then P (warp-private rows)

    const int qt  = blockIdx.x;        // 0..31
    const int h   = blockIdx.y;
    const int b   = blockIdx.z;
    const int tid = threadIdx.x;
    const int warp = tid >> 5;
    const int lane = tid & 31;
    const int g   = lane >> 2;
    const int tig = lane & 3;
    const int qr0 = warp * 16 + g;     // this thread's row pair: qr0, qr0+8

    const float* Qg = g_q + ((size_t)(b * NHEAD + h) * SEQ + qt * 64) * HDIM;
    const float* Kg = g_k + (size_t)(b * NHEAD + h) * SEQ * HDIM;
    const float* Vg = g_v + (size_t)(b * NHEAD + h) * SEQ * HDIM;
    const float* mbase = mask + (size_t)b * SEQ;

    // Stage Q tile into Ps (64x64, stride BSTR)
    #pragma unroll
    for (int t = 0; t < 8; t++) {
        int f = tid + t * 128;             // 0..1023 float4s
        int r = f >> 4, c4 = (f & 15) * 4;
        *(float4*)&Ps[r * BSTR + c4] = *(const float4*)(Qg + r * HDIM + c4);
    }
    __syncthreads();

    // Gather Q A-fragments once (tf32-rounded); warp-private rows.
    uint32_t qa[8][4];
    #pragma unroll
    for (int ks = 0; ks < 8; ks++) {
        const int kb = ks * 8;
        qa[ks][0] = __float_as_uint(tf32r(Ps[ qr0      * BSTR + kb + tig    ]));
        qa[ks][1] = __float_as_uint(tf32r(Ps[(qr0 + 8) * BSTR + kb + tig    ]));
        qa[ks][2] = __float_as_uint(tf32r(Ps[ qr0      * BSTR + kb + tig + 4]));
        qa[ks][3] = __float_as_uint(tf32r(Ps[(qr0 + 8) * BSTR + kb + tig + 4]));
    }

    float m0 = -1e30f, m1 = -1e30f, l0 = 0.f, l1 = 0.f;
    float o[8][4];
    #pragma unroll
    for (int nf = 0; nf < 8; nf++)
        #pragma unroll
        for (int i = 0; i < 4; i++) o[nf][i] = 0.f;

    for (int kt = 0; kt < SEQ / 64; kt++) {
        __syncthreads();   // prior tile's Vs/Ks reads complete (also covers Q gather)
        // Stage K,V tiles (tf32-rounded)
        #pragma unroll
        for (int t = 0; t < 8; t++) {
            int f = tid + t * 128;
            int r = f >> 4, c4 = (f & 15) * 4;
            float4 kv = *(const float4*)(Kg + (size_t)(kt * 64 + r) * HDIM + c4);
            kv.x = tf32r(kv.x); kv.y = tf32r(kv.y); kv.z = tf32r(kv.z); kv.w = tf32r(kv.w);
            *(float4*)&Ks[r * BSTR + c4] = kv;
            float4 vv = *(const float4*)(Vg + (size_t)(kt * 64 + r) * HDIM + c4);
            vv.x = tf32r(vv.x); vv.y = tf32r(vv.y); vv.z = tf32r(vv.z); vv.w = tf32r(vv.w);
            *(float4*)&Vs[r * BSTR + c4] = vv;
        }
        __syncthreads();

        // S = Q K^T  (per warp: 16 x 64)
        float c[8][4];
        #pragma unroll
        for (int nf = 0; nf < 8; nf++)
            #pragma unroll
            for (int i = 0; i < 4; i++) c[nf][i] = 0.f;

        #pragma unroll
        for (int ks = 0; ks < 8; ks++) {
            const int kb = ks * 8;
            #pragma unroll
            for (int nf = 0; nf < 8; nf++) {
                uint32_t b0 = __float_as_uint(Ks[(nf * 8 + g) * BSTR + kb + tig    ]);
                uint32_t b1 = __float_as_uint(Ks[(nf * 8 + g) * BSTR + kb + tig + 4]);
                mma_tf32(c[nf], qa[ks][0], qa[ks][1], qa[ks][2], qa[ks][3], b0, b1);
            }
        }

        // scale + mask (mask indexed by key position)
        const float* mrow = mbase + kt * 64;
        #pragma unroll
        for (int nf = 0; nf < 8; nf++) {
            float mk0 = mrow[nf * 8 + 2 * tig];
            float mk1 = mrow[nf * 8 + 2 * tig + 1];
            c[nf][0] = c[nf][0] * 0.125f + mk0;
            c[nf][1] = c[nf][1] * 0.125f + mk1;
            c[nf][2] = c[nf][2] * 0.125f + mk0;
            c[nf][3] = c[nf][3] * 0.125f + mk1;
        }

        // online softmax: rows qr0 (c0,c1) and qr0+8 (c2,c3)
        float t0 = -1e30f, t1 = -1e30f;
        #pragma unroll
        for (int nf = 0; nf < 8; nf++) {
            t0 = fmaxf(t0, fmaxf(c[nf][0], c[nf][1]));
            t1 = fmaxf(t1, fmaxf(c[nf][2], c[nf][3]));
        }
        t0 = fmaxf(t0, __shfl_xor_sync(0xffffffffu, t0, 1));
        t0 = fmaxf(t0, __shfl_xor_sync(0xffffffffu, t0, 2));
        t1 = fmaxf(t1, __shfl_xor_sync(0xffffffffu, t1, 1));
        t1 = fmaxf(t1, __shfl_xor_sync(0xffffffffu, t1, 2));
        float nm0 = fmaxf(m0, t0), nm1 = fmaxf(m1, t1);

        float rs0 = 0.f, rs1 = 0.f;
        #pragma unroll
        for (int nf = 0; nf < 8; nf++) {
            c[nf][0] = __expf(c[nf][0] - nm0);
            c[nf][1] = __expf(c[nf][1] - nm0);
            c[nf][2] = __expf(c[nf][2] - nm1);
            c[nf][3] = __expf(c[nf][3] - nm1);
            rs0 += c[nf][0] + c[nf][1];
            rs1 += c[nf][2] + c[nf][3];
        }
        rs0 += __shfl_xor_sync(0xffffffffu, rs0, 1);
        rs0 += __shfl_xor_sync(0xffffffffu, rs0, 2);
        rs1 += __shfl_xor_sync(0xffffffffu, rs1, 1);
        rs1 += __shfl_xor_sync(0xffffffffu, rs1, 2);

        float a0 = __expf(m0 - nm0), a1 = __expf(m1 - nm1);
        l0 = l0 * a0 + rs0;  m0 = nm0;
        l1 = l1 * a1 + rs1;  m1 = nm1;

        #pragma unroll
        for (int nf = 0; nf < 8; nf++) {
            o[nf][0] *= a0; o[nf][1] *= a0;
            o[nf][2] *= a1; o[nf][3] *= a1;
        }

        // store P (tf32) into warp-private smem rows
        #pragma unroll
        for (int nf = 0; nf < 8; nf++) {
            float2 p0; p0.x = tf32r(c[nf][0]); p0.y = tf32r(c[nf][1]);
            float2 p1; p1.x = tf32r(c[nf][2]); p1.y = tf32r(c[nf][3]);
            *(float2*)&Ps[ qr0      * BSTR + nf * 8 + 2 * tig] = p0;
            *(float2*)&Ps[(qr0 + 8) * BSTR + nf * 8 + 2 * tig] = p1;
        }
        __syncwarp();

        // O += P V
        #pragma unroll
        for (int ks = 0; ks < 8; ks++) {
            const int kb = ks * 8;
            uint32_t pa0 = __float_as_uint(Ps[ qr0      * BSTR + kb + tig    ]);
            uint32_t pa1 = __float_as_uint(Ps[(qr0 + 8) * BSTR + kb + tig    ]);
            uint32_t pa2 = __float_as_uint(Ps[ qr0      * BSTR + kb + tig + 4]);
            uint32_t pa3 = __float_as_uint(Ps[(qr0 + 8) * BSTR + kb + tig + 4]);
            #pragma unroll
            for (int nf = 0; nf < 8; nf++) {
                uint32_t b0 = __float_as_uint(Vs[(kb + tig    ) * BSTR + nf * 8 + g]);
                uint32_t b1 = __float_as_uint(Vs[(kb + tig + 4) * BSTR + nf * 8 + g]);
                mma_tf32(o[nf], pa0, pa1, pa2, pa3, b0, b1);
            }
        }
        __syncwarp();   // P reads done before next iteration's P writes
    }

    // Final normalize and scatter to ctx[B*S, D] (col = h*64 + hd)
    const float inv0 = 1.f / l0, inv1 = 1.f / l1;
    const int row0 = qt * 64 + qr0;
    #pragma unroll
    for (int nf = 0; nf < 8; nf++) {
        const int col = h * HDIM + nf * 8 + 2 * tig;
        float2 v0; v0.x = o[nf][0] * inv0; v0.y = o[nf][1] * inv0;
        float2 v1; v1.x = o[nf][2] * inv1; v1.y = o[nf][3] * inv1;
        *(float2*)&g_ctx[((size_t)b * SEQ + row0    ) * DMODEL + col] = v0;
        *(float2*)&g_ctx[((size_t)b * SEQ + row0 + 8) * DMODEL + col] = v1;
    }
}

// ---------------------------------------------------------------------------
extern "C" void kernel_launch(void* const* d_in, const int* in_sizes, int n_in,
                              void* d_out, int out_size)
{
    const float* x    = (const float*)d_in[0];
    const float* mask = (const float*)d_in[1];
    const float* Wq   = (const float*)d_in[2];
    const float* bq   = (const float*)d_in[3];
    const float* Wk   = (const float*)d_in[4];
    const float* bk   = (const float*)d_in[5];
    const float* Wv   = (const float*)d_in[6];
    const float* bv   = (const float*)d_in[7];
    const float* Wo   = (const float*)d_in[8];
    const float* bo   = (const float*)d_in[9];
    float* out = (float*)d_out;

    (void)in_sizes; (void)n_in; (void)out_size;

    // Host-side config (not a stream op; legal under graph capture).
    cudaFuncSetAttribute(attn_mma, cudaFuncAttributeMaxDynamicSharedMemorySize,
                         ATT_SMEM_BYTES);

    // 1) QKV projections (mma.sync tf32; z selects Q/K/V)
    gemm_tc<0><<<dim3(DMODEL / BN, MROWS / BM, 3), 256>>>(
        x, Wq, bq, Wk, bk, Wv, bv, nullptr);

    // 2) Flash attention (mma.sync tf32)
    attn_mma<<<dim3(SEQ / 64, NHEAD, BATCH), 128, ATT_SMEM_BYTES>>>(mask);

    // 3) Output projection (mma.sync tf32)
    gemm_tc<1><<<dim3(DMODEL / BN, MROWS / BM), 256>>>(
        nullptr, Wo, bo, nullptr, nullptr, nullptr, nullptr, out);
}